// round 5
// baseline (speedup 1.0000x reference)
#include <cuda_runtime.h>
#include <cuda_bf16.h>
#include <cstdint>

#define NN   50000
#define EE   800000
#define CIN  64
#define CH   128
#define COUT 2
#define GG   512

#define NTILES   ((NN + 127) / 128)   // 391
#define GRID_G   148

// ---------------- scratch (static device globals; no allocation) -------------
__device__ float g_hA[NN * CH];
__device__ float g_hB[NN * CH];
__device__ int   g_deg[NN];
__device__ int   g_rowptr[NN + 1];
__device__ int   g_cursor[NN];
__device__ int   g_col[EE];
__device__ int   g_gcnt[GG];
__device__ float g_gsum[GG * CH];
// pre-transposed, bf16-split weights, linear [N=128][K=256] per conv
__device__ __nv_bfloat16 g_Bhi[12 * 32768];
__device__ __nv_bfloat16 g_Blo[12 * 32768];

// ---------------- preprocessing (3 kernels total) -----------------------------
// 1) zero counters + weight prep (transpose [K,N]->[N,K] concat, bf16 hi/lo split)
__global__ void k_init_prepw(const float* __restrict__ Wl0, const float* __restrict__ Wr0,
                             const float* __restrict__ Wl, const float* __restrict__ Wr) {
    int idx = blockIdx.x * blockDim.x + threadIdx.x;
    if (idx < NN) { g_deg[idx] = 0; g_cursor[idx] = 0; }
    if (idx < GG) g_gcnt[idx] = 0;
    if (idx < GG * CH) g_gsum[idx] = 0.f;
    if (idx >= 12 * 32768) return;
    int ci = idx >> 15;
    int r  = idx & 32767;
    int j  = r >> 8;      // out col (0..127) -> B row n
    int k  = r & 255;     // concat K index
    float w = 0.f;
    if (ci == 0) {
        if (k < CIN)                  w = Wl0[k * CH + j];
        else if (k >= 128 && k < 192) w = Wr0[(k - 128) * CH + j];
    } else {
        int li = ci - 1;
        if (k < 128) w = Wl[((size_t)li * CH + k) * CH + j];
        else         w = Wr[((size_t)li * CH + (k - 128)) * CH + j];
    }
    __nv_bfloat16 hi = __float2bfloat16(w);
    __nv_bfloat16 lo = __float2bfloat16(w - __bfloat162float(hi));
    g_Bhi[idx] = hi;
    g_Blo[idx] = lo;
}

// 2) degree count + per-graph node count
__global__ void k_count2(const int* __restrict__ dst, const int* __restrict__ batch) {
    int i = blockIdx.x * blockDim.x + threadIdx.x;
    if (i < EE) atomicAdd(&g_deg[dst[i]], 1);
    if (i < NN) atomicAdd(&g_gcnt[batch[i]], 1);
}

// 3) single-block scan of degrees -> rowptr, then CSR fill
__global__ void __launch_bounds__(1024, 1)
k_scanfill(const int* __restrict__ src, const int* __restrict__ dst) {
    __shared__ int s[1024];
    __shared__ int carry;
    int tid = threadIdx.x;
    if (tid == 0) { carry = 0; g_rowptr[0] = 0; }
    __syncthreads();
    for (int base = 0; base < NN; base += 1024) {
        int idx = base + tid;
        int v = (idx < NN) ? g_deg[idx] : 0;
        s[tid] = v;
        __syncthreads();
        for (int off = 1; off < 1024; off <<= 1) {
            int t = (tid >= off) ? s[tid - off] : 0;
            __syncthreads();
            s[tid] += t;
            __syncthreads();
        }
        int inc = s[tid] + carry;
        if (idx < NN) g_rowptr[idx + 1] = inc;
        __syncthreads();
        if (tid == 1023) carry = inc;
        __syncthreads();
    }
    // CSR fill
    for (int e = tid; e < EE; e += 1024) {
        int d = dst[e];
        int pos = g_rowptr[d] + atomicAdd(&g_cursor[d], 1);
        g_col[pos] = src[e];
    }
}

// ---------------- fused layer: agg-gather + HMMA split-3 dual GEMM ------------
// out[m,:] = mean_nbr(X)[m,:] @ Wl + X[m,:] @ Wr + b ; activation
// A = [agg | h] concat K=256; D = Ahi*Bhi + Ahi*Blo + Alo*Bhi, fp32 acc.
// ACT: 0 none, 1 relu, 2 leaky(0.01), 3 none + global pool (atomic into g_gsum)
#define SB_STR 264              // bf16 units — conflict-free frag loads
#define SA_STR 136
#define SMO_BH 0
#define SMO_BL (128 * SB_STR * 2)
#define SMO_AH (2 * 128 * SB_STR * 2)
#define SMO_AL (2 * 128 * SB_STR * 2 + 128 * SA_STR * 2)
#define SM_TOT (2 * 128 * SB_STR * 2 + 2 * 128 * SA_STR * 2)  // 204800 B

__device__ __forceinline__ void mma16816(float* d, const uint32_t* a,
                                         uint32_t b0, uint32_t b1) {
    asm volatile(
        "mma.sync.aligned.m16n8k16.row.col.f32.bf16.bf16.f32 "
        "{%0,%1,%2,%3}, {%4,%5,%6,%7}, {%8,%9}, {%0,%1,%2,%3};"
        : "+f"(d[0]), "+f"(d[1]), "+f"(d[2]), "+f"(d[3])
        : "r"(a[0]), "r"(a[1]), "r"(a[2]), "r"(a[3]), "r"(b0), "r"(b1));
}

__device__ __forceinline__ uint32_t packbf2(float x, float y) {
    __nv_bfloat16 a = __float2bfloat16(x), b = __float2bfloat16(y);
    return ((uint32_t)__bfloat16_as_ushort(b) << 16) | __bfloat16_as_ushort(a);
}

template <int KIN, int ACT>
__global__ void __launch_bounds__(256, 1)
k_layer(const float* __restrict__ X, const int* __restrict__ batch,
        const __nv_bfloat16* __restrict__ Bhi, const __nv_bfloat16* __restrict__ Blo,
        const float* __restrict__ bias, float* __restrict__ out) {
    extern __shared__ char sm[];
    __nv_bfloat16* sBh = (__nv_bfloat16*)(sm + SMO_BH);
    __nv_bfloat16* sBl = (__nv_bfloat16*)(sm + SMO_BL);
    __nv_bfloat16* sAh = (__nv_bfloat16*)(sm + SMO_AH);
    __nv_bfloat16* sAl = (__nv_bfloat16*)(sm + SMO_AL);

    const int tid = threadIdx.x;
    const int wid = tid >> 5, lid = tid & 31;
    const int g = lid >> 2, tig = lid & 3;
    const int m0 = (wid & 3) * 32;        // warp row origin within tile
    const int n0 = (wid >> 2) * 64;       // warp col origin

    // resident B (hi+lo) -> padded SMEM
    for (int i = tid; i < 4096; i += 256) {
        int n = i >> 5, kq = i & 31;
        float4 vh = ((const float4*)Bhi)[i];
        float4 vl = ((const float4*)Blo)[i];
        *(float4*)&sBh[n * SB_STR + kq * 8] = vh;
        *(float4*)&sBl[n * SB_STR + kq * 8] = vl;
    }

    const uint32_t* uBh = (const uint32_t*)sBh;
    const uint32_t* uBl = (const uint32_t*)sBl;
    const uint32_t* uAh = (const uint32_t*)sAh;
    const uint32_t* uAl = (const uint32_t*)sAl;
    constexpr int KSTEPS = (KIN == 64) ? 4 : 8;

    for (int t = blockIdx.x; t < NTILES; t += GRID_G) {
        const int row0 = t * 128;
        float acc[2][8][4];
#pragma unroll
        for (int mt = 0; mt < 2; mt++)
#pragma unroll
            for (int nt = 0; nt < 8; nt++)
#pragma unroll
                for (int q = 0; q < 4; q++) acc[mt][nt][q] = 0.f;

        for (int s = 0; s < 2; s++) {
            __syncthreads();   // prior chunk's frag loads done before restage
            if (s == 0) {
                // ---- fused mean-aggregate gather into sA ----
                if (KIN == 128) {
                    const int c4 = lid * 4;
#pragma unroll 1
                    for (int rr = 0; rr < 16; rr++) {
                        int row = (wid << 4) + rr;
                        int gr = row0 + row;
                        float a0 = 0.f, a1 = 0.f, a2 = 0.f, a3 = 0.f;
                        float b0 = 0.f, b1 = 0.f, b2 = 0.f, b3 = 0.f;
                        if (gr < NN) {
                            int js = g_rowptr[gr], je = g_rowptr[gr + 1];
                            int j = js;
                            for (; j + 2 <= je; j += 2) {
                                int u0 = g_col[j], u1 = g_col[j + 1];
                                float4 v0 = *(const float4*)(X + (size_t)u0 * 128 + c4);
                                float4 v1 = *(const float4*)(X + (size_t)u1 * 128 + c4);
                                a0 += v0.x; a1 += v0.y; a2 += v0.z; a3 += v0.w;
                                b0 += v1.x; b1 += v1.y; b2 += v1.z; b3 += v1.w;
                            }
                            if (j < je) {
                                float4 v0 = *(const float4*)(X + (size_t)g_col[j] * 128 + c4);
                                a0 += v0.x; a1 += v0.y; a2 += v0.z; a3 += v0.w;
                            }
                            float inv = (je > js) ? 1.f / (float)(je - js) : 0.f;
                            a0 = (a0 + b0) * inv; a1 = (a1 + b1) * inv;
                            a2 = (a2 + b2) * inv; a3 = (a3 + b3) * inv;
                        }
                        float h0 = __bfloat162float(__float2bfloat16(a0));
                        float h1 = __bfloat162float(__float2bfloat16(a1));
                        float h2 = __bfloat162float(__float2bfloat16(a2));
                        float h3 = __bfloat162float(__float2bfloat16(a3));
                        uint2 uh = make_uint2(packbf2(a0, a1), packbf2(a2, a3));
                        uint2 ul = make_uint2(packbf2(a0 - h0, a1 - h1), packbf2(a2 - h2, a3 - h3));
                        *(uint2*)&sAh[row * SA_STR + c4] = uh;
                        *(uint2*)&sAl[row * SA_STR + c4] = ul;
                    }
                } else {  // KIN == 64
                    const int c2 = lid * 2;
#pragma unroll 1
                    for (int rr = 0; rr < 16; rr++) {
                        int row = (wid << 4) + rr;
                        int gr = row0 + row;
                        float a0 = 0.f, a1 = 0.f, b0 = 0.f, b1 = 0.f;
                        if (gr < NN) {
                            int js = g_rowptr[gr], je = g_rowptr[gr + 1];
                            int j = js;
                            for (; j + 2 <= je; j += 2) {
                                int u0 = g_col[j], u1 = g_col[j + 1];
                                float2 v0 = *(const float2*)(X + (size_t)u0 * 64 + c2);
                                float2 v1 = *(const float2*)(X + (size_t)u1 * 64 + c2);
                                a0 += v0.x; a1 += v0.y;
                                b0 += v1.x; b1 += v1.y;
                            }
                            if (j < je) {
                                float2 v0 = *(const float2*)(X + (size_t)g_col[j] * 64 + c2);
                                a0 += v0.x; a1 += v0.y;
                            }
                            float inv = (je > js) ? 1.f / (float)(je - js) : 0.f;
                            a0 = (a0 + b0) * inv; a1 = (a1 + b1) * inv;
                        }
                        float h0 = __bfloat162float(__float2bfloat16(a0));
                        float h1 = __bfloat162float(__float2bfloat16(a1));
                        *(uint32_t*)&sAh[row * SA_STR + c2] = packbf2(a0, a1);
                        *(uint32_t*)&sAl[row * SA_STR + c2] = packbf2(a0 - h0, a1 - h1);
                    }
                }
            } else {
                // ---- plain copy of X rows (self term) ----
                const int NIT = (KIN == 64) ? 2048 : 4096;
                const int QM = (KIN == 64) ? 15 : 31;
                const int QS = (KIN == 64) ? 4 : 5;
                for (int it = tid; it < NIT; it += 256) {
                    int row = it >> QS, k0 = (it & QM) * 4;
                    float4 v = make_float4(0.f, 0.f, 0.f, 0.f);
                    int gr = row0 + row;
                    if (gr < NN)
                        v = *(const float4*)(X + (size_t)gr * KIN + k0);
                    float h0 = __bfloat162float(__float2bfloat16(v.x));
                    float h1 = __bfloat162float(__float2bfloat16(v.y));
                    float h2 = __bfloat162float(__float2bfloat16(v.z));
                    float h3 = __bfloat162float(__float2bfloat16(v.w));
                    *(uint2*)&sAh[row * SA_STR + k0] =
                        make_uint2(packbf2(v.x, v.y), packbf2(v.z, v.w));
                    *(uint2*)&sAl[row * SA_STR + k0] =
                        make_uint2(packbf2(v.x - h0, v.y - h1), packbf2(v.z - h2, v.w - h3));
                }
            }
            __syncthreads();

#pragma unroll
            for (int ks = 0; ks < KSTEPS; ks++) {
                const int k0 = ks * 16;
                uint32_t ah[2][4], al[2][4];
#pragma unroll
                for (int mt = 0; mt < 2; mt++) {
                    int r = m0 + mt * 16 + g;
                    int ai = r * (SA_STR / 2) + (k0 >> 1) + tig;
                    ah[mt][0] = uAh[ai];
                    ah[mt][1] = uAh[ai + 8 * (SA_STR / 2)];
                    ah[mt][2] = uAh[ai + 4];
                    ah[mt][3] = uAh[ai + 8 * (SA_STR / 2) + 4];
                    al[mt][0] = uAl[ai];
                    al[mt][1] = uAl[ai + 8 * (SA_STR / 2)];
                    al[mt][2] = uAl[ai + 4];
                    al[mt][3] = uAl[ai + 8 * (SA_STR / 2) + 4];
                }
                const int kg = s * 128 + k0;
#pragma unroll
                for (int nt = 0; nt < 8; nt++) {
                    int c = n0 + nt * 8 + g;
                    int bi = c * (SB_STR / 2) + (kg >> 1) + tig;
                    uint32_t bh0 = uBh[bi], bh1 = uBh[bi + 4];
                    uint32_t bl0 = uBl[bi], bl1 = uBl[bi + 4];
#pragma unroll
                    for (int mt = 0; mt < 2; mt++) {
                        mma16816(acc[mt][nt], ah[mt], bh0, bh1);
                        mma16816(acc[mt][nt], ah[mt], bl0, bl1);
                        mma16816(acc[mt][nt], al[mt], bh0, bh1);
                    }
                }
            }
        }

        // epilogue: bias + activation + store (or pool)
#pragma unroll
        for (int mt = 0; mt < 2; mt++) {
#pragma unroll
            for (int half = 0; half < 2; half++) {
                int gr = row0 + m0 + mt * 16 + g + half * 8;
                if (gr < NN) {
                    int bidx = (ACT == 3) ? __ldg(batch + gr) : 0;
#pragma unroll
                    for (int nt = 0; nt < 8; nt++) {
                        int c = n0 + nt * 8 + tig * 2;
                        float v0 = acc[mt][nt][half * 2 + 0] + __ldg(bias + c);
                        float v1 = acc[mt][nt][half * 2 + 1] + __ldg(bias + c + 1);
                        if (ACT == 1) {
                            v0 = fmaxf(v0, 0.f); v1 = fmaxf(v1, 0.f);
                        } else if (ACT == 2) {
                            v0 = (v0 > 0.f) ? v0 : 0.01f * v0;
                            v1 = (v1 > 0.f) ? v1 : 0.01f * v1;
                        }
                        if (ACT == 3) {
                            atomicAdd(&g_gsum[bidx * CH + c], v0);
                            atomicAdd(&g_gsum[bidx * CH + c + 1], v1);
                        } else {
                            *(float2*)(out + (size_t)gr * CH + c) = make_float2(v0, v1);
                        }
                    }
                }
            }
        }
    }
}

// ---------------- head --------------------------------------------------------
__global__ void k_head(const float* __restrict__ headW,
                       const float* __restrict__ headb,
                       float* __restrict__ out) {
    int tid = blockIdx.x * blockDim.x + threadIdx.x;
    if (tid >= GG * COUT) return;
    int g = tid >> 1;
    int o = tid & 1;
    float cnt = (float)g_gcnt[g];
    float inv = 1.f / fmaxf(cnt, 1.f);
    float acc = headb[o];
#pragma unroll 8
    for (int k = 0; k < CH; k++)
        acc += g_gsum[g * CH + k] * inv * headW[k * COUT + o];
    out[tid] = acc;
}

// ---------------- host driver -------------------------------------------------
extern "C" void kernel_launch(void* const* d_in, const int* in_sizes, int n_in,
                              void* d_out, int out_size) {
    const float* x     = (const float*)d_in[0];
    const int*   ei    = (const int*)d_in[1];
    const int*   srcp  = ei;
    const int*   dstp  = ei + EE;
    const int*   batch = (const int*)d_in[2];
    const float* Wl0   = (const float*)d_in[3];
    const float* Wr0   = (const float*)d_in[4];
    const float* b0    = (const float*)d_in[5];
    const float* Wl    = (const float*)d_in[6];
    const float* Wr    = (const float*)d_in[7];
    const float* bb    = (const float*)d_in[8];
    const float* headW = (const float*)d_in[9];
    const float* headb = (const float*)d_in[10];
    float* out = (float*)d_out;

    float *hA, *hB;
    __nv_bfloat16 *Bhi, *Blo;
    cudaGetSymbolAddress((void**)&hA, g_hA);
    cudaGetSymbolAddress((void**)&hB, g_hB);
    cudaGetSymbolAddress((void**)&Bhi, g_Bhi);
    cudaGetSymbolAddress((void**)&Blo, g_Blo);

    cudaFuncSetAttribute(k_layer<64, 1>,  cudaFuncAttributeMaxDynamicSharedMemorySize, SM_TOT);
    cudaFuncSetAttribute(k_layer<128, 1>, cudaFuncAttributeMaxDynamicSharedMemorySize, SM_TOT);
    cudaFuncSetAttribute(k_layer<128, 2>, cudaFuncAttributeMaxDynamicSharedMemorySize, SM_TOT);
    cudaFuncSetAttribute(k_layer<128, 3>, cudaFuncAttributeMaxDynamicSharedMemorySize, SM_TOT);

    // --- preprocessing: 3 launches ---
    k_init_prepw<<<(12 * 32768 + 255) / 256, 256>>>(Wl0, Wr0, Wl, Wr);
    k_count2<<<(EE + 255) / 256, 256>>>(dstp, batch);
    k_scanfill<<<1, 1024>>>(srcp, dstp);

    // --- conv 0: fused agg + GEMM, C_IN=64 -> 128, ReLU ---
    k_layer<64, 1><<<GRID_G, 256, SM_TOT>>>(x, batch, Bhi, Blo, b0, hA);

    // --- convs 1..11 (conv 11 fuses the global mean pool) ---
    const int act[11] = {1, 1, 2, 1, 1, 1, 2, 1, 1, 1, 3};
    const float* cur = hA;
    float* nxt = hB;
    for (int li = 0; li < 11; li++) {
        const __nv_bfloat16* bh = Bhi + (size_t)(li + 1) * 32768;
        const __nv_bfloat16* bl = Blo + (size_t)(li + 1) * 32768;
        const float* bi = bb + (size_t)li * CH;
        if (act[li] == 1)
            k_layer<128, 1><<<GRID_G, 256, SM_TOT>>>(cur, batch, bh, bl, bi, nxt);
        else if (act[li] == 2)
            k_layer<128, 2><<<GRID_G, 256, SM_TOT>>>(cur, batch, bh, bl, bi, nxt);
        else
            k_layer<128, 3><<<GRID_G, 256, SM_TOT>>>(cur, batch, bh, bl, bi, nxt);
        const float* t = cur;
        cur = nxt;
        nxt = (float*)t;
    }

    // --- head ---
    k_head<<<(GG * COUT + 255) / 256, 256>>>(headW, headb, out);
}

// round 6
// speedup vs baseline: 1.2447x; 1.2447x over previous
#include <cuda_runtime.h>
#include <cuda_bf16.h>
#include <cstdint>

#define NN   50000
#define EE   800000
#define CIN  64
#define CH   128
#define COUT 2
#define GG   512

#define NTILES   ((NN + 127) / 128)   // 391
#define GRID_G   148

// ---------------- scratch (static device globals; no allocation) -------------
__device__ float g_hA[NN * CH];
__device__ float g_hB[NN * CH];
__device__ float g_agg[NN * CH];
__device__ int   g_deg[NN];
__device__ int   g_rowptr[NN + 1];
__device__ int   g_cursor[NN];
__device__ int   g_col[EE];
__device__ int   g_gcnt[GG];
__device__ float g_gsum[GG * CH];
// pre-transposed, bf16-split weights, linear [N=128][K=256] per conv
__device__ __nv_bfloat16 g_Bhi[12 * 32768];
__device__ __nv_bfloat16 g_Blo[12 * 32768];

// ---------------- preprocessing (3 kernels total) -----------------------------
__global__ void k_init_prepw(const float* __restrict__ Wl0, const float* __restrict__ Wr0,
                             const float* __restrict__ Wl, const float* __restrict__ Wr) {
    int idx = blockIdx.x * blockDim.x + threadIdx.x;
    if (idx < NN) { g_deg[idx] = 0; g_cursor[idx] = 0; }
    if (idx < GG) g_gcnt[idx] = 0;
    if (idx < GG * CH) g_gsum[idx] = 0.f;
    if (idx >= 12 * 32768) return;
    int ci = idx >> 15;
    int r  = idx & 32767;
    int j  = r >> 8;      // out col (0..127) -> B row n
    int k  = r & 255;     // concat K index
    float w = 0.f;
    if (ci == 0) {
        if (k < CIN)                  w = Wl0[k * CH + j];
        else if (k >= 128 && k < 192) w = Wr0[(k - 128) * CH + j];
    } else {
        int li = ci - 1;
        if (k < 128) w = Wl[((size_t)li * CH + k) * CH + j];
        else         w = Wr[((size_t)li * CH + (k - 128)) * CH + j];
    }
    __nv_bfloat16 hi = __float2bfloat16(w);
    __nv_bfloat16 lo = __float2bfloat16(w - __bfloat162float(hi));
    g_Bhi[idx] = hi;
    g_Blo[idx] = lo;
}

__global__ void k_count2(const int* __restrict__ dst, const int* __restrict__ batch) {
    int i = blockIdx.x * blockDim.x + threadIdx.x;
    if (i < EE) atomicAdd(&g_deg[dst[i]], 1);
    if (i < NN) atomicAdd(&g_gcnt[batch[i]], 1);
}

__global__ void __launch_bounds__(1024, 1)
k_scanfill(const int* __restrict__ src, const int* __restrict__ dst) {
    __shared__ int s[1024];
    __shared__ int carry;
    int tid = threadIdx.x;
    if (tid == 0) { carry = 0; g_rowptr[0] = 0; }
    __syncthreads();
    for (int base = 0; base < NN; base += 1024) {
        int idx = base + tid;
        int v = (idx < NN) ? g_deg[idx] : 0;
        s[tid] = v;
        __syncthreads();
        for (int off = 1; off < 1024; off <<= 1) {
            int t = (tid >= off) ? s[tid - off] : 0;
            __syncthreads();
            s[tid] += t;
            __syncthreads();
        }
        int inc = s[tid] + carry;
        if (idx < NN) g_rowptr[idx + 1] = inc;
        __syncthreads();
        if (tid == 1023) carry = inc;
        __syncthreads();
    }
    for (int e = tid; e < EE; e += 1024) {
        int d = dst[e];
        int pos = g_rowptr[d] + atomicAdd(&g_cursor[d], 1);
        g_col[pos] = src[e];
    }
}

// ---------------- neighbor mean aggregation (warp per node) -------------------
// K=128: lane covers 4 channels (float4). K=64: lane covers 2 (float2).
template <int K>
__global__ void __launch_bounds__(256, 8)
k_agg(const float* __restrict__ h, float* __restrict__ agg) {
    int node = blockIdx.x * 8 + (threadIdx.x >> 5);
    int lid = threadIdx.x & 31;
    if (node >= NN) return;
    int js = g_rowptr[node], je = g_rowptr[node + 1];
    if (K == 128) {
        const int c = lid * 4;
        float a0 = 0.f, a1 = 0.f, a2 = 0.f, a3 = 0.f;
        float b0 = 0.f, b1 = 0.f, b2 = 0.f, b3 = 0.f;
        int j = js;
        for (; j + 4 <= je; j += 4) {
            int u0 = g_col[j], u1 = g_col[j + 1], u2 = g_col[j + 2], u3 = g_col[j + 3];
            float4 v0 = *(const float4*)(h + (size_t)u0 * 128 + c);
            float4 v1 = *(const float4*)(h + (size_t)u1 * 128 + c);
            float4 v2 = *(const float4*)(h + (size_t)u2 * 128 + c);
            float4 v3 = *(const float4*)(h + (size_t)u3 * 128 + c);
            a0 += v0.x; a1 += v0.y; a2 += v0.z; a3 += v0.w;
            b0 += v1.x; b1 += v1.y; b2 += v1.z; b3 += v1.w;
            a0 += v2.x; a1 += v2.y; a2 += v2.z; a3 += v2.w;
            b0 += v3.x; b1 += v3.y; b2 += v3.z; b3 += v3.w;
        }
        for (; j < je; j++) {
            float4 v0 = *(const float4*)(h + (size_t)g_col[j] * 128 + c);
            a0 += v0.x; a1 += v0.y; a2 += v0.z; a3 += v0.w;
        }
        float inv = (je > js) ? 1.f / (float)(je - js) : 0.f;
        float4 o;
        o.x = (a0 + b0) * inv; o.y = (a1 + b1) * inv;
        o.z = (a2 + b2) * inv; o.w = (a3 + b3) * inv;
        *(float4*)(agg + (size_t)node * 128 + c) = o;
    } else {
        const int c = lid * 2;
        float a0 = 0.f, a1 = 0.f, b0 = 0.f, b1 = 0.f;
        int j = js;
        for (; j + 4 <= je; j += 4) {
            int u0 = g_col[j], u1 = g_col[j + 1], u2 = g_col[j + 2], u3 = g_col[j + 3];
            float2 v0 = *(const float2*)(h + (size_t)u0 * 64 + c);
            float2 v1 = *(const float2*)(h + (size_t)u1 * 64 + c);
            float2 v2 = *(const float2*)(h + (size_t)u2 * 64 + c);
            float2 v3 = *(const float2*)(h + (size_t)u3 * 64 + c);
            a0 += v0.x; a1 += v0.y;
            b0 += v1.x; b1 += v1.y;
            a0 += v2.x; a1 += v2.y;
            b0 += v3.x; b1 += v3.y;
        }
        for (; j < je; j++) {
            float2 v0 = *(const float2*)(h + (size_t)g_col[j] * 64 + c);
            a0 += v0.x; a1 += v0.y;
        }
        float inv = (je > js) ? 1.f / (float)(je - js) : 0.f;
        *(float2*)(agg + (size_t)node * 64 + c) =
            make_float2((a0 + b0) * inv, (a1 + b1) * inv);
    }
}

// ---------------- HMMA bf16 split-3 dual GEMM --------------------------------
// out[m,:] = agg @ Wl + h @ Wr + b ; activation.
// ACT: 0 none, 1 relu, 2 leaky(0.01), 3 none + fused global pool
#define SB_STR 264
#define SA_STR 136
#define SMO_BH 0
#define SMO_BL (128 * SB_STR * 2)
#define SMO_AH (2 * 128 * SB_STR * 2)
#define SMO_AL (2 * 128 * SB_STR * 2 + 128 * SA_STR * 2)
#define SM_TOT (2 * 128 * SB_STR * 2 + 2 * 128 * SA_STR * 2)  // 204800 B

__device__ __forceinline__ void mma16816(float* d, const uint32_t* a,
                                         uint32_t b0, uint32_t b1) {
    asm volatile(
        "mma.sync.aligned.m16n8k16.row.col.f32.bf16.bf16.f32 "
        "{%0,%1,%2,%3}, {%4,%5,%6,%7}, {%8,%9}, {%0,%1,%2,%3};"
        : "+f"(d[0]), "+f"(d[1]), "+f"(d[2]), "+f"(d[3])
        : "r"(a[0]), "r"(a[1]), "r"(a[2]), "r"(a[3]), "r"(b0), "r"(b1));
}

__device__ __forceinline__ uint32_t packbf2(float x, float y) {
    __nv_bfloat16 a = __float2bfloat16(x), b = __float2bfloat16(y);
    return ((uint32_t)__bfloat16_as_ushort(b) << 16) | __bfloat16_as_ushort(a);
}

template <int KIN, int ACT>
__global__ void __launch_bounds__(256, 1)
k_hgemm(const float* __restrict__ Xa, const float* __restrict__ Xh,
        const int* __restrict__ batch,
        const __nv_bfloat16* __restrict__ Bhi, const __nv_bfloat16* __restrict__ Blo,
        const float* __restrict__ bias, float* __restrict__ out) {
    extern __shared__ char sm[];
    __nv_bfloat16* sBh = (__nv_bfloat16*)(sm + SMO_BH);
    __nv_bfloat16* sBl = (__nv_bfloat16*)(sm + SMO_BL);
    __nv_bfloat16* sAh = (__nv_bfloat16*)(sm + SMO_AH);
    __nv_bfloat16* sAl = (__nv_bfloat16*)(sm + SMO_AL);

    const int tid = threadIdx.x;
    const int wid = tid >> 5, lid = tid & 31;
    const int g = lid >> 2, tig = lid & 3;
    const int m0 = (wid & 3) * 32;
    const int n0 = (wid >> 2) * 64;

    for (int i = tid; i < 4096; i += 256) {
        int n = i >> 5, kq = i & 31;
        float4 vh = ((const float4*)Bhi)[i];
        float4 vl = ((const float4*)Blo)[i];
        *(float4*)&sBh[n * SB_STR + kq * 8] = vh;
        *(float4*)&sBl[n * SB_STR + kq * 8] = vl;
    }

    const uint32_t* uBh = (const uint32_t*)sBh;
    const uint32_t* uBl = (const uint32_t*)sBl;
    const uint32_t* uAh = (const uint32_t*)sAh;
    const uint32_t* uAl = (const uint32_t*)sAl;
    constexpr int KSTEPS = (KIN == 64) ? 4 : 8;

    for (int t = blockIdx.x; t < NTILES; t += GRID_G) {
        const int row0 = t * 128;
        float acc[2][8][4];
#pragma unroll
        for (int mt = 0; mt < 2; mt++)
#pragma unroll
            for (int nt = 0; nt < 8; nt++)
#pragma unroll
                for (int q = 0; q < 4; q++) acc[mt][nt][q] = 0.f;

        for (int s = 0; s < 2; s++) {
            const float* X = s ? Xh : Xa;
            __syncthreads();
            for (int it = tid; it < 4096; it += 256) {
                int row = it >> 5, k0 = (it & 31) * 4;
                float4 v = make_float4(0.f, 0.f, 0.f, 0.f);
                int gr = row0 + row;
                if (gr < NN && k0 < KIN)
                    v = *(const float4*)(X + (size_t)gr * KIN + k0);
                float h0 = __bfloat162float(__float2bfloat16(v.x));
                float h1 = __bfloat162float(__float2bfloat16(v.y));
                float h2 = __bfloat162float(__float2bfloat16(v.z));
                float h3 = __bfloat162float(__float2bfloat16(v.w));
                *(uint2*)&sAh[row * SA_STR + k0] =
                    make_uint2(packbf2(v.x, v.y), packbf2(v.z, v.w));
                *(uint2*)&sAl[row * SA_STR + k0] =
                    make_uint2(packbf2(v.x - h0, v.y - h1), packbf2(v.z - h2, v.w - h3));
            }
            __syncthreads();

#pragma unroll
            for (int ks = 0; ks < KSTEPS; ks++) {
                const int k0 = ks * 16;
                uint32_t ah[2][4], al[2][4];
#pragma unroll
                for (int mt = 0; mt < 2; mt++) {
                    int r = m0 + mt * 16 + g;
                    int ai = r * (SA_STR / 2) + (k0 >> 1) + tig;
                    ah[mt][0] = uAh[ai];
                    ah[mt][1] = uAh[ai + 8 * (SA_STR / 2)];
                    ah[mt][2] = uAh[ai + 4];
                    ah[mt][3] = uAh[ai + 8 * (SA_STR / 2) + 4];
                    al[mt][0] = uAl[ai];
                    al[mt][1] = uAl[ai + 8 * (SA_STR / 2)];
                    al[mt][2] = uAl[ai + 4];
                    al[mt][3] = uAl[ai + 8 * (SA_STR / 2) + 4];
                }
                const int kg = s * 128 + k0;
#pragma unroll
                for (int nt = 0; nt < 8; nt++) {
                    int c = n0 + nt * 8 + g;
                    int bi = c * (SB_STR / 2) + (kg >> 1) + tig;
                    uint32_t bh0 = uBh[bi], bh1 = uBh[bi + 4];
                    uint32_t bl0 = uBl[bi], bl1 = uBl[bi + 4];
#pragma unroll
                    for (int mt = 0; mt < 2; mt++) {
                        mma16816(acc[mt][nt], ah[mt], bh0, bh1);
                        mma16816(acc[mt][nt], ah[mt], bl0, bl1);
                        mma16816(acc[mt][nt], al[mt], bh0, bh1);
                    }
                }
            }
        }

        // epilogue: bias + activation + store (or fused pool)
#pragma unroll
        for (int mt = 0; mt < 2; mt++) {
#pragma unroll
            for (int half = 0; half < 2; half++) {
                int gr = row0 + m0 + mt * 16 + g + half * 8;
                if (gr < NN) {
                    int bidx = (ACT == 3) ? __ldg(batch + gr) : 0;
#pragma unroll
                    for (int nt = 0; nt < 8; nt++) {
                        int c = n0 + nt * 8 + tig * 2;
                        float v0 = acc[mt][nt][half * 2 + 0] + __ldg(bias + c);
                        float v1 = acc[mt][nt][half * 2 + 1] + __ldg(bias + c + 1);
                        if (ACT == 1) {
                            v0 = fmaxf(v0, 0.f); v1 = fmaxf(v1, 0.f);
                        } else if (ACT == 2) {
                            v0 = (v0 > 0.f) ? v0 : 0.01f * v0;
                            v1 = (v1 > 0.f) ? v1 : 0.01f * v1;
                        }
                        if (ACT == 3) {
                            atomicAdd(&g_gsum[bidx * CH + c], v0);
                            atomicAdd(&g_gsum[bidx * CH + c + 1], v1);
                        } else {
                            *(float2*)(out + (size_t)gr * CH + c) = make_float2(v0, v1);
                        }
                    }
                }
            }
        }
    }
}

// ---------------- head --------------------------------------------------------
__global__ void k_head(const float* __restrict__ headW,
                       const float* __restrict__ headb,
                       float* __restrict__ out) {
    int tid = blockIdx.x * blockDim.x + threadIdx.x;
    if (tid >= GG * COUT) return;
    int g = tid >> 1;
    int o = tid & 1;
    float cnt = (float)g_gcnt[g];
    float inv = 1.f / fmaxf(cnt, 1.f);
    float acc = headb[o];
#pragma unroll 8
    for (int k = 0; k < CH; k++)
        acc += g_gsum[g * CH + k] * inv * headW[k * COUT + o];
    out[tid] = acc;
}

// ---------------- host driver -------------------------------------------------
extern "C" void kernel_launch(void* const* d_in, const int* in_sizes, int n_in,
                              void* d_out, int out_size) {
    const float* x     = (const float*)d_in[0];
    const int*   ei    = (const int*)d_in[1];
    const int*   srcp  = ei;
    const int*   dstp  = ei + EE;
    const int*   batch = (const int*)d_in[2];
    const float* Wl0   = (const float*)d_in[3];
    const float* Wr0   = (const float*)d_in[4];
    const float* b0    = (const float*)d_in[5];
    const float* Wl    = (const float*)d_in[6];
    const float* Wr    = (const float*)d_in[7];
    const float* bb    = (const float*)d_in[8];
    const float* headW = (const float*)d_in[9];
    const float* headb = (const float*)d_in[10];
    float* out = (float*)d_out;

    float *hA, *hB, *agg;
    __nv_bfloat16 *Bhi, *Blo;
    cudaGetSymbolAddress((void**)&hA, g_hA);
    cudaGetSymbolAddress((void**)&hB, g_hB);
    cudaGetSymbolAddress((void**)&agg, g_agg);
    cudaGetSymbolAddress((void**)&Bhi, g_Bhi);
    cudaGetSymbolAddress((void**)&Blo, g_Blo);

    cudaFuncSetAttribute(k_hgemm<64, 1>,  cudaFuncAttributeMaxDynamicSharedMemorySize, SM_TOT);
    cudaFuncSetAttribute(k_hgemm<128, 1>, cudaFuncAttributeMaxDynamicSharedMemorySize, SM_TOT);
    cudaFuncSetAttribute(k_hgemm<128, 2>, cudaFuncAttributeMaxDynamicSharedMemorySize, SM_TOT);
    cudaFuncSetAttribute(k_hgemm<128, 3>, cudaFuncAttributeMaxDynamicSharedMemorySize, SM_TOT);

    // --- preprocessing: 3 launches ---
    k_init_prepw<<<(12 * 32768 + 255) / 256, 256>>>(Wl0, Wr0, Wl, Wr);
    k_count2<<<(EE + 255) / 256, 256>>>(dstp, batch);
    k_scanfill<<<1, 1024>>>(srcp, dstp);

    // --- conv 0: C_IN=64 -> 128, ReLU ---
    k_agg<64><<<(NN + 7) / 8, 256>>>(x, agg);
    k_hgemm<64, 1><<<GRID_G, 256, SM_TOT>>>(agg, x, batch, Bhi, Blo, b0, hA);

    // --- convs 1..11 (conv 11 fuses global mean pool) ---
    const int act[11] = {1, 1, 2, 1, 1, 1, 2, 1, 1, 1, 3};
    const float* cur = hA;
    float* nxt = hB;
    for (int li = 0; li < 11; li++) {
        k_agg<128><<<(NN + 7) / 8, 256>>>(cur, agg);
        const __nv_bfloat16* bh = Bhi + (size_t)(li + 1) * 32768;
        const __nv_bfloat16* bl = Blo + (size_t)(li + 1) * 32768;
        const float* bi = bb + (size_t)li * CH;
        if (act[li] == 1)
            k_hgemm<128, 1><<<GRID_G, 256, SM_TOT>>>(agg, cur, batch, bh, bl, bi, nxt);
        else if (act[li] == 2)
            k_hgemm<128, 2><<<GRID_G, 256, SM_TOT>>>(agg, cur, batch, bh, bl, bi, nxt);
        else
            k_hgemm<128, 3><<<GRID_G, 256, SM_TOT>>>(agg, cur, batch, bh, bl, bi, nxt);
        const float* t = cur;
        cur = nxt;
        nxt = (float*)t;
    }

    // --- head ---
    k_head<<<(GG * COUT + 255) / 256, 256>>>(headW, headb, out);
}

// round 7
// speedup vs baseline: 2.8011x; 2.2504x over previous
#include <cuda_runtime.h>
#include <cuda_bf16.h>
#include <cstdint>

#define NN   50000
#define EE   800000
#define CIN  64
#define CH   128
#define COUT 2
#define GG   512

#define NTILES   ((NN + 127) / 128)   // 391
#define GRID_G   148

// ---------------- scratch (static device globals; no allocation) -------------
__device__ float g_hA[NN * CH];
__device__ float g_hB[NN * CH];
__device__ float g_agg[NN * CH];
__device__ int   g_deg[NN];
__device__ int   g_inc[NN];
__device__ int   g_rowptr[NN + 1];
__device__ int   g_cursor[NN];
__device__ int   g_col[EE];
__device__ int   g_bsum[64];
__device__ int   g_gcnt[GG];
__device__ float g_gsum[GG * CH];
// pre-transposed, bf16-split weights, linear [N=128][K=256] per conv
__device__ __nv_bfloat16 g_Bhi[12 * 32768];
__device__ __nv_bfloat16 g_Blo[12 * 32768];

// ---------------- preprocessing (grid-parallel, 6 kernels) --------------------
__global__ void k_init_prepw(const float* __restrict__ Wl0, const float* __restrict__ Wr0,
                             const float* __restrict__ Wl, const float* __restrict__ Wr) {
    int idx = blockIdx.x * blockDim.x + threadIdx.x;
    if (idx < NN) { g_deg[idx] = 0; g_cursor[idx] = 0; }
    if (idx < GG) g_gcnt[idx] = 0;
    if (idx < GG * CH) g_gsum[idx] = 0.f;
    if (idx >= 12 * 32768) return;
    int ci = idx >> 15;
    int r  = idx & 32767;
    int j  = r >> 8;      // out col (0..127) -> B row n
    int k  = r & 255;     // concat K index
    float w = 0.f;
    if (ci == 0) {
        if (k < CIN)                  w = Wl0[k * CH + j];
        else if (k >= 128 && k < 192) w = Wr0[(k - 128) * CH + j];
    } else {
        int li = ci - 1;
        if (k < 128) w = Wl[((size_t)li * CH + k) * CH + j];
        else         w = Wr[((size_t)li * CH + (k - 128)) * CH + j];
    }
    __nv_bfloat16 hi = __float2bfloat16(w);
    __nv_bfloat16 lo = __float2bfloat16(w - __bfloat162float(hi));
    g_Bhi[idx] = hi;
    g_Blo[idx] = lo;
}

__global__ void k_count2(const int* __restrict__ dst, const int* __restrict__ batch) {
    int i = blockIdx.x * blockDim.x + threadIdx.x;
    if (i < EE) atomicAdd(&g_deg[dst[i]], 1);
    if (i < NN) atomicAdd(&g_gcnt[batch[i]], 1);
}

__global__ void k_scan1() {
    __shared__ int s[1024];
    int tid = threadIdx.x;
    int idx = blockIdx.x * 1024 + tid;
    int v = (idx < NN) ? g_deg[idx] : 0;
    s[tid] = v;
    __syncthreads();
    for (int off = 1; off < 1024; off <<= 1) {
        int t = (tid >= off) ? s[tid - off] : 0;
        __syncthreads();
        s[tid] += t;
        __syncthreads();
    }
    if (idx < NN) g_inc[idx] = s[tid];
    if (tid == 1023) g_bsum[blockIdx.x] = s[1023];
}

__global__ void k_scan2(int nb) {
    if (threadIdx.x == 0 && blockIdx.x == 0) {
        int run = 0;
        for (int i = 0; i < nb; i++) { int v = g_bsum[i]; g_bsum[i] = run; run += v; }
    }
}

__global__ void k_scan3() {
    int i = blockIdx.x * blockDim.x + threadIdx.x;
    if (i < NN) g_rowptr[i + 1] = g_inc[i] + g_bsum[i >> 10];
    if (i == 0) g_rowptr[0] = 0;
}

__global__ void k_fill(const int* __restrict__ src, const int* __restrict__ dst) {
    int e = blockIdx.x * blockDim.x + threadIdx.x;
    if (e < EE) {
        int d = dst[e];
        int pos = g_rowptr[d] + atomicAdd(&g_cursor[d], 1);
        g_col[pos] = src[e];
    }
}

// ---------------- neighbor mean aggregation (warp per node) -------------------
template <int K>
__global__ void __launch_bounds__(256, 8)
k_agg(const float* __restrict__ h, float* __restrict__ agg) {
    int node = blockIdx.x * 8 + (threadIdx.x >> 5);
    int lid = threadIdx.x & 31;
    if (node >= NN) return;
    int js = g_rowptr[node], je = g_rowptr[node + 1];
    if (K == 128) {
        const int c = lid * 4;
        float a0 = 0.f, a1 = 0.f, a2 = 0.f, a3 = 0.f;
        float b0 = 0.f, b1 = 0.f, b2 = 0.f, b3 = 0.f;
        int j = js;
        for (; j + 4 <= je; j += 4) {
            int u0 = g_col[j], u1 = g_col[j + 1], u2 = g_col[j + 2], u3 = g_col[j + 3];
            float4 v0 = *(const float4*)(h + (size_t)u0 * 128 + c);
            float4 v1 = *(const float4*)(h + (size_t)u1 * 128 + c);
            float4 v2 = *(const float4*)(h + (size_t)u2 * 128 + c);
            float4 v3 = *(const float4*)(h + (size_t)u3 * 128 + c);
            a0 += v0.x; a1 += v0.y; a2 += v0.z; a3 += v0.w;
            b0 += v1.x; b1 += v1.y; b2 += v1.z; b3 += v1.w;
            a0 += v2.x; a1 += v2.y; a2 += v2.z; a3 += v2.w;
            b0 += v3.x; b1 += v3.y; b2 += v3.z; b3 += v3.w;
        }
        for (; j < je; j++) {
            float4 v0 = *(const float4*)(h + (size_t)g_col[j] * 128 + c);
            a0 += v0.x; a1 += v0.y; a2 += v0.z; a3 += v0.w;
        }
        float inv = (je > js) ? 1.f / (float)(je - js) : 0.f;
        float4 o;
        o.x = (a0 + b0) * inv; o.y = (a1 + b1) * inv;
        o.z = (a2 + b2) * inv; o.w = (a3 + b3) * inv;
        *(float4*)(agg + (size_t)node * 128 + c) = o;
    } else {
        const int c = lid * 2;
        float a0 = 0.f, a1 = 0.f, b0 = 0.f, b1 = 0.f;
        int j = js;
        for (; j + 4 <= je; j += 4) {
            int u0 = g_col[j], u1 = g_col[j + 1], u2 = g_col[j + 2], u3 = g_col[j + 3];
            float2 v0 = *(const float2*)(h + (size_t)u0 * 64 + c);
            float2 v1 = *(const float2*)(h + (size_t)u1 * 64 + c);
            float2 v2 = *(const float2*)(h + (size_t)u2 * 64 + c);
            float2 v3 = *(const float2*)(h + (size_t)u3 * 64 + c);
            a0 += v0.x; a1 += v0.y;
            b0 += v1.x; b1 += v1.y;
            a0 += v2.x; a1 += v2.y;
            b0 += v3.x; b1 += v3.y;
        }
        for (; j < je; j++) {
            float2 v0 = *(const float2*)(h + (size_t)g_col[j] * 64 + c);
            a0 += v0.x; a1 += v0.y;
        }
        float inv = (je > js) ? 1.f / (float)(je - js) : 0.f;
        *(float2*)(agg + (size_t)node * 64 + c) =
            make_float2((a0 + b0) * inv, (a1 + b1) * inv);
    }
}

// ---------------- HMMA bf16 split-3 dual GEMM --------------------------------
// out[m,:] = agg @ Wl + h @ Wr + b ; activation.
// ACT: 0 none, 1 relu, 2 leaky(0.01), 3 none + fused global pool
#define SB_STR 264
#define SA_STR 136
#define SMO_BH 0
#define SMO_BL (128 * SB_STR * 2)
#define SMO_AH (2 * 128 * SB_STR * 2)
#define SMO_AL (2 * 128 * SB_STR * 2 + 128 * SA_STR * 2)
#define SM_TOT (2 * 128 * SB_STR * 2 + 2 * 128 * SA_STR * 2)  // 204800 B

__device__ __forceinline__ void mma16816(float* d, const uint32_t* a,
                                         uint32_t b0, uint32_t b1) {
    asm volatile(
        "mma.sync.aligned.m16n8k16.row.col.f32.bf16.bf16.f32 "
        "{%0,%1,%2,%3}, {%4,%5,%6,%7}, {%8,%9}, {%0,%1,%2,%3};"
        : "+f"(d[0]), "+f"(d[1]), "+f"(d[2]), "+f"(d[3])
        : "r"(a[0]), "r"(a[1]), "r"(a[2]), "r"(a[3]), "r"(b0), "r"(b1));
}

__device__ __forceinline__ uint32_t packbf2(float x, float y) {
    __nv_bfloat16 a = __float2bfloat16(x), b = __float2bfloat16(y);
    return ((uint32_t)__bfloat16_as_ushort(b) << 16) | __bfloat16_as_ushort(a);
}

template <int KIN, int ACT>
__global__ void __launch_bounds__(256, 1)
k_hgemm(const float* __restrict__ Xa, const float* __restrict__ Xh,
        const int* __restrict__ batch,
        const __nv_bfloat16* __restrict__ Bhi, const __nv_bfloat16* __restrict__ Blo,
        const float* __restrict__ bias, float* __restrict__ out) {
    extern __shared__ char sm[];
    __nv_bfloat16* sBh = (__nv_bfloat16*)(sm + SMO_BH);
    __nv_bfloat16* sBl = (__nv_bfloat16*)(sm + SMO_BL);
    __nv_bfloat16* sAh = (__nv_bfloat16*)(sm + SMO_AH);
    __nv_bfloat16* sAl = (__nv_bfloat16*)(sm + SMO_AL);

    const int tid = threadIdx.x;
    const int wid = tid >> 5, lid = tid & 31;
    const int g = lid >> 2, tig = lid & 3;
    const int m0 = (wid & 3) * 32;
    const int n0 = (wid >> 2) * 64;

    for (int i = tid; i < 4096; i += 256) {
        int n = i >> 5, kq = i & 31;
        float4 vh = ((const float4*)Bhi)[i];
        float4 vl = ((const float4*)Blo)[i];
        *(float4*)&sBh[n * SB_STR + kq * 8] = vh;
        *(float4*)&sBl[n * SB_STR + kq * 8] = vl;
    }

    const uint32_t* uBh = (const uint32_t*)sBh;
    const uint32_t* uBl = (const uint32_t*)sBl;
    const uint32_t* uAh = (const uint32_t*)sAh;
    const uint32_t* uAl = (const uint32_t*)sAl;
    constexpr int KSTEPS = (KIN == 64) ? 4 : 8;

    for (int t = blockIdx.x; t < NTILES; t += GRID_G) {
        const int row0 = t * 128;
        float acc[2][8][4];
#pragma unroll
        for (int mt = 0; mt < 2; mt++)
#pragma unroll
            for (int nt = 0; nt < 8; nt++)
#pragma unroll
                for (int q = 0; q < 4; q++) acc[mt][nt][q] = 0.f;

        for (int s = 0; s < 2; s++) {
            const float* X = s ? Xh : Xa;
            __syncthreads();
            for (int it = tid; it < 4096; it += 256) {
                int row = it >> 5, k0 = (it & 31) * 4;
                float4 v = make_float4(0.f, 0.f, 0.f, 0.f);
                int gr = row0 + row;
                if (gr < NN && k0 < KIN)
                    v = *(const float4*)(X + (size_t)gr * KIN + k0);
                float h0 = __bfloat162float(__float2bfloat16(v.x));
                float h1 = __bfloat162float(__float2bfloat16(v.y));
                float h2 = __bfloat162float(__float2bfloat16(v.z));
                float h3 = __bfloat162float(__float2bfloat16(v.w));
                *(uint2*)&sAh[row * SA_STR + k0] =
                    make_uint2(packbf2(v.x, v.y), packbf2(v.z, v.w));
                *(uint2*)&sAl[row * SA_STR + k0] =
                    make_uint2(packbf2(v.x - h0, v.y - h1), packbf2(v.z - h2, v.w - h3));
            }
            __syncthreads();

#pragma unroll
            for (int ks = 0; ks < KSTEPS; ks++) {
                const int k0 = ks * 16;
                uint32_t ah[2][4], al[2][4];
#pragma unroll
                for (int mt = 0; mt < 2; mt++) {
                    int r = m0 + mt * 16 + g;
                    int ai = r * (SA_STR / 2) + (k0 >> 1) + tig;
                    ah[mt][0] = uAh[ai];
                    ah[mt][1] = uAh[ai + 8 * (SA_STR / 2)];
                    ah[mt][2] = uAh[ai + 4];
                    ah[mt][3] = uAh[ai + 8 * (SA_STR / 2) + 4];
                    al[mt][0] = uAl[ai];
                    al[mt][1] = uAl[ai + 8 * (SA_STR / 2)];
                    al[mt][2] = uAl[ai + 4];
                    al[mt][3] = uAl[ai + 8 * (SA_STR / 2) + 4];
                }
                const int kg = s * 128 + k0;
#pragma unroll
                for (int nt = 0; nt < 8; nt++) {
                    int c = n0 + nt * 8 + g;
                    int bi = c * (SB_STR / 2) + (kg >> 1) + tig;
                    uint32_t bh0 = uBh[bi], bh1 = uBh[bi + 4];
                    uint32_t bl0 = uBl[bi], bl1 = uBl[bi + 4];
#pragma unroll
                    for (int mt = 0; mt < 2; mt++) {
                        mma16816(acc[mt][nt], ah[mt], bh0, bh1);
                        mma16816(acc[mt][nt], ah[mt], bl0, bl1);
                        mma16816(acc[mt][nt], al[mt], bh0, bh1);
                    }
                }
            }
        }

        // epilogue: bias + activation + store (or fused pool)
#pragma unroll
        for (int mt = 0; mt < 2; mt++) {
#pragma unroll
            for (int half = 0; half < 2; half++) {
                int gr = row0 + m0 + mt * 16 + g + half * 8;
                if (gr < NN) {
                    int bidx = (ACT == 3) ? __ldg(batch + gr) : 0;
#pragma unroll
                    for (int nt = 0; nt < 8; nt++) {
                        int c = n0 + nt * 8 + tig * 2;
                        float v0 = acc[mt][nt][half * 2 + 0] + __ldg(bias + c);
                        float v1 = acc[mt][nt][half * 2 + 1] + __ldg(bias + c + 1);
                        if (ACT == 1) {
                            v0 = fmaxf(v0, 0.f); v1 = fmaxf(v1, 0.f);
                        } else if (ACT == 2) {
                            v0 = (v0 > 0.f) ? v0 : 0.01f * v0;
                            v1 = (v1 > 0.f) ? v1 : 0.01f * v1;
                        }
                        if (ACT == 3) {
                            atomicAdd(&g_gsum[bidx * CH + c], v0);
                            atomicAdd(&g_gsum[bidx * CH + c + 1], v1);
                        } else {
                            *(float2*)(out + (size_t)gr * CH + c) = make_float2(v0, v1);
                        }
                    }
                }
            }
        }
    }
}

// ---------------- head --------------------------------------------------------
__global__ void k_head(const float* __restrict__ headW,
                       const float* __restrict__ headb,
                       float* __restrict__ out) {
    int tid = blockIdx.x * blockDim.x + threadIdx.x;
    if (tid >= GG * COUT) return;
    int g = tid >> 1;
    int o = tid & 1;
    float cnt = (float)g_gcnt[g];
    float inv = 1.f / fmaxf(cnt, 1.f);
    float acc = headb[o];
#pragma unroll 8
    for (int k = 0; k < CH; k++)
        acc += g_gsum[g * CH + k] * inv * headW[k * COUT + o];
    out[tid] = acc;
}

// ---------------- host driver -------------------------------------------------
extern "C" void kernel_launch(void* const* d_in, const int* in_sizes, int n_in,
                              void* d_out, int out_size) {
    const float* x     = (const float*)d_in[0];
    const int*   ei    = (const int*)d_in[1];
    const int*   srcp  = ei;
    const int*   dstp  = ei + EE;
    const int*   batch = (const int*)d_in[2];
    const float* Wl0   = (const float*)d_in[3];
    const float* Wr0   = (const float*)d_in[4];
    const float* b0    = (const float*)d_in[5];
    const float* Wl    = (const float*)d_in[6];
    const float* Wr    = (const float*)d_in[7];
    const float* bb    = (const float*)d_in[8];
    const float* headW = (const float*)d_in[9];
    const float* headb = (const float*)d_in[10];
    float* out = (float*)d_out;

    float *hA, *hB, *agg;
    __nv_bfloat16 *Bhi, *Blo;
    cudaGetSymbolAddress((void**)&hA, g_hA);
    cudaGetSymbolAddress((void**)&hB, g_hB);
    cudaGetSymbolAddress((void**)&agg, g_agg);
    cudaGetSymbolAddress((void**)&Bhi, g_Bhi);
    cudaGetSymbolAddress((void**)&Blo, g_Blo);

    cudaFuncSetAttribute(k_hgemm<64, 1>,  cudaFuncAttributeMaxDynamicSharedMemorySize, SM_TOT);
    cudaFuncSetAttribute(k_hgemm<128, 1>, cudaFuncAttributeMaxDynamicSharedMemorySize, SM_TOT);
    cudaFuncSetAttribute(k_hgemm<128, 2>, cudaFuncAttributeMaxDynamicSharedMemorySize, SM_TOT);
    cudaFuncSetAttribute(k_hgemm<128, 3>, cudaFuncAttributeMaxDynamicSharedMemorySize, SM_TOT);

    // --- preprocessing: grid-parallel, 6 launches ---
    k_init_prepw<<<(12 * 32768 + 255) / 256, 256>>>(Wl0, Wr0, Wl, Wr);
    k_count2<<<(EE + 255) / 256, 256>>>(dstp, batch);
    k_scan1<<<(NN + 1023) / 1024, 1024>>>();
    k_scan2<<<1, 32>>>((NN + 1023) / 1024);
    k_scan3<<<(NN + 255) / 256, 256>>>();
    k_fill<<<(EE + 255) / 256, 256>>>(srcp, dstp);

    // --- conv 0: C_IN=64 -> 128, ReLU ---
    k_agg<64><<<(NN + 7) / 8, 256>>>(x, agg);
    k_hgemm<64, 1><<<GRID_G, 256, SM_TOT>>>(agg, x, batch, Bhi, Blo, b0, hA);

    // --- convs 1..11 (conv 11 fuses global mean pool) ---
    const int act[11] = {1, 1, 2, 1, 1, 1, 2, 1, 1, 1, 3};
    const float* cur = hA;
    float* nxt = hB;
    for (int li = 0; li < 11; li++) {
        k_agg<128><<<(NN + 7) / 8, 256>>>(cur, agg);
        const __nv_bfloat16* bh = Bhi + (size_t)(li + 1) * 32768;
        const __nv_bfloat16* bl = Blo + (size_t)(li + 1) * 32768;
        const float* bi = bb + (size_t)li * CH;
        if (act[li] == 1)
            k_hgemm<128, 1><<<GRID_G, 256, SM_TOT>>>(agg, cur, batch, bh, bl, bi, nxt);
        else if (act[li] == 2)
            k_hgemm<128, 2><<<GRID_G, 256, SM_TOT>>>(agg, cur, batch, bh, bl, bi, nxt);
        else
            k_hgemm<128, 3><<<GRID_G, 256, SM_TOT>>>(agg, cur, batch, bh, bl, bi, nxt);
        const float* t = cur;
        cur = nxt;
        nxt = (float*)t;
    }

    // --- head ---
    k_head<<<(GG * COUT + 255) / 256, 256>>>(headW, headb, out);
}